// round 1
// baseline (speedup 1.0000x reference)
#include <cuda_runtime.h>

// Problem constants
#define B_   2
#define S_   2048
#define D_   1024
#define NH_  16
#define HD_  64
#define M_   4096           // B*S
#define SS_  4194304        // S*S
#define HEADSZ_ (2048*64)   // S*HD = 131072

// ---------------- scratch (__device__ globals; allocation-free) ----------------
__device__ float g_lin3[3u * 4096u * 1024u];     // 48 MB: q/k/v linear outputs [p][m][n]
__device__ float g_qkv[3u * 32u * 2048u * 64u];  // 48 MB: head layout [p*32+bh][s][d]
__device__ float g_scores[134217728u];           // 537 MB: [bh][l][n] scores -> probs
__device__ float g_attn[32u * 2048u * 64u];      // 16 MB: [bh][s][d]
__device__ float g_attnT[4096u * 1024u];         // 16 MB: interleaved [m][d*16+h]

// XOR bank swizzle: word index permutation s.t. both stride-1 and stride-16
// accesses over a 1024-float row are bank-conflict-free.
__device__ __forceinline__ int swz(int n) { return n ^ ((n >> 5) & 31); }

// ---------------- GEMM: C[4096,1024] = A[4096,1024] @ W[1024,1024] + bias ----------------
// asel >= 0 : A = g_attnT (output projection). csel >= 0 : C = g_lin3 + csel*4M.
__global__ void __launch_bounds__(256) gemm_nk1024(const float* __restrict__ A,
                                                   const float* __restrict__ W,
                                                   const float* __restrict__ bias,
                                                   float* __restrict__ C,
                                                   int asel, int csel)
{
    if (asel >= 0) A = g_attnT;
    if (csel >= 0) C = g_lin3 + (size_t)csel * 4194304u;

    __shared__ float As[16][128];
    __shared__ float Ws[16][128];
    const int tid = threadIdx.x;
    const int tx = tid & 15, ty = tid >> 4;
    const int mBase = blockIdx.y * 128, nBase = blockIdx.x * 128;

    float acc[8][8] = {};

    for (int k0 = 0; k0 < 1024; k0 += 16) {
#pragma unroll
        for (int i = 0; i < 2; i++) {
            int f4 = tid + i * 256;
            int ar = f4 >> 2, ac = (f4 & 3) * 4;
            float4 va = *(const float4*)(A + (size_t)(mBase + ar) * 1024 + k0 + ac);
            As[ac + 0][ar] = va.x; As[ac + 1][ar] = va.y;
            As[ac + 2][ar] = va.z; As[ac + 3][ar] = va.w;
            int wr = f4 >> 5, wc = (f4 & 31) * 4;
            *(float4*)&Ws[wr][wc] = *(const float4*)(W + (size_t)(k0 + wr) * 1024 + nBase + wc);
        }
        __syncthreads();
#pragma unroll
        for (int kk = 0; kk < 16; kk++) {
            float a[8], b[8];
            *(float4*)&a[0] = *(float4*)&As[kk][ty * 8];
            *(float4*)&a[4] = *(float4*)&As[kk][ty * 8 + 4];
            *(float4*)&b[0] = *(float4*)&Ws[kk][tx * 8];
            *(float4*)&b[4] = *(float4*)&Ws[kk][tx * 8 + 4];
#pragma unroll
            for (int i = 0; i < 8; i++)
#pragma unroll
                for (int j = 0; j < 8; j++)
                    acc[i][j] += a[i] * b[j];
        }
        __syncthreads();
    }

#pragma unroll
    for (int i = 0; i < 8; i++) {
        int row = mBase + ty * 8 + i;
#pragma unroll
        for (int j = 0; j < 8; j += 4) {
            int col = nBase + tx * 8 + j;
            float4 v;
            v.x = acc[i][j + 0] + bias[col + 0];
            v.y = acc[i][j + 1] + bias[col + 1];
            v.z = acc[i][j + 2] + bias[col + 2];
            v.w = acc[i][j + 3] + bias[col + 3];
            *(float4*)(C + (size_t)row * 1024 + col) = v;
        }
    }
}

// ---------------- interleaved [m][d*16+h] -> head layout [p*32+bh][s][d] ----------------
__global__ void __launch_bounds__(256) trans_qkv_kernel()
{
    __shared__ float buf[8][1024];
    const int w = threadIdx.x >> 5, lane = threadIdx.x & 31;
    const int r = blockIdx.x * 8 + w;      // 0 .. 3*4096-1
    const int p = r >> 12;
    const int bs = r & 4095;
    const int b = bs >> 11, s = bs & 2047;

    const float* src = g_lin3 + (size_t)r * 1024;
#pragma unroll
    for (int i = 0; i < 8; i++) {
        int n0 = i * 128 + lane * 4;
        float4 v = *(const float4*)(src + n0);
        buf[w][swz(n0 + 0)] = v.x;
        buf[w][swz(n0 + 1)] = v.y;
        buf[w][swz(n0 + 2)] = v.z;
        buf[w][swz(n0 + 3)] = v.w;
    }
    __syncwarp();
    float* dstBase = g_qkv + ((size_t)p * 32 + (size_t)b * 16) * HEADSZ_ + (size_t)s * 64;
#pragma unroll
    for (int h = 0; h < 16; h++) {
        float* dst = dstBase + (size_t)h * HEADSZ_;
#pragma unroll
        for (int half = 0; half < 2; half++) {
            int d = half * 32 + lane;
            dst[d] = buf[w][swz(d * 16 + h)];
        }
    }
}

// ---------------- scores[bh][l][n] = (Q_h @ K_h^T) / 8 ----------------
__global__ void __launch_bounds__(256) qk_kernel()
{
    __shared__ float Qs[16][128];
    __shared__ float Ks[16][128];
    const int tid = threadIdx.x;
    const int tx = tid & 15, ty = tid >> 4;
    const int bh = blockIdx.z;
    const int mBase = blockIdx.y * 128, nBase = blockIdx.x * 128;
    const float* Q = g_qkv + (size_t)bh * HEADSZ_;
    const float* K = g_qkv + (size_t)(32 + bh) * HEADSZ_;

    float acc[8][8] = {};

    for (int k0 = 0; k0 < 64; k0 += 16) {
#pragma unroll
        for (int i = 0; i < 2; i++) {
            int f4 = tid + i * 256;
            int ar = f4 >> 2, ac = (f4 & 3) * 4;
            float4 vq = *(const float4*)(Q + (size_t)(mBase + ar) * 64 + k0 + ac);
            Qs[ac + 0][ar] = vq.x; Qs[ac + 1][ar] = vq.y;
            Qs[ac + 2][ar] = vq.z; Qs[ac + 3][ar] = vq.w;
            float4 vk = *(const float4*)(K + (size_t)(nBase + ar) * 64 + k0 + ac);
            Ks[ac + 0][ar] = vk.x; Ks[ac + 1][ar] = vk.y;
            Ks[ac + 2][ar] = vk.z; Ks[ac + 3][ar] = vk.w;
        }
        __syncthreads();
#pragma unroll
        for (int kk = 0; kk < 16; kk++) {
            float a[8], b[8];
            *(float4*)&a[0] = *(float4*)&Qs[kk][ty * 8];
            *(float4*)&a[4] = *(float4*)&Qs[kk][ty * 8 + 4];
            *(float4*)&b[0] = *(float4*)&Ks[kk][tx * 8];
            *(float4*)&b[4] = *(float4*)&Ks[kk][tx * 8 + 4];
#pragma unroll
            for (int i = 0; i < 8; i++)
#pragma unroll
                for (int j = 0; j < 8; j++)
                    acc[i][j] += a[i] * b[j];
        }
        __syncthreads();
    }

    float* Cp = g_scores + (size_t)bh * SS_;
#pragma unroll
    for (int i = 0; i < 8; i++) {
        int row = mBase + ty * 8 + i;
#pragma unroll
        for (int j = 0; j < 8; j += 4) {
            int col = nBase + tx * 8 + j;
            float4 v;
            v.x = acc[i][j + 0] * 0.125f;
            v.y = acc[i][j + 1] * 0.125f;
            v.z = acc[i][j + 2] * 0.125f;
            v.w = acc[i][j + 3] * 0.125f;
            *(float4*)(Cp + (size_t)row * 2048 + col) = v;
        }
    }
}

// ---------------- softmax over the 16-head axis ----------------
// Reads 16 strided planes, writes exact probs to d_out ([b,l,n,h], contiguous)
// and normalized values back into g_scores ([bh][l][n]) for the AV GEMM.
__global__ void __launch_bounds__(256) softmax_kernel(float* __restrict__ probs_out)
{
    const size_t idx = (size_t)blockIdx.x * 256 + threadIdx.x; // (b*S+l)*S+n, < 8388608
    const int b = (int)(idx >> 22);
    const size_t ln = idx & 4194303u;
    const size_t base = (size_t)b * 16u * SS_ + ln;

    float v[16];
    float mx = -1e30f;
#pragma unroll
    for (int h = 0; h < 16; h++) {
        v[h] = g_scores[base + (size_t)h * SS_];
        mx = fmaxf(mx, v[h]);
    }
    float sum = 0.f;
#pragma unroll
    for (int h = 0; h < 16; h++) {
        v[h] = __expf(v[h] - mx);
        sum += v[h];
    }
    const float inv = 1.0f / sum;
#pragma unroll
    for (int h = 0; h < 16; h++) v[h] *= inv;

#pragma unroll
    for (int h = 0; h < 16; h++) g_scores[base + (size_t)h * SS_] = v[h];

    if (probs_out) {
        float4* dst = (float4*)(probs_out + idx * 16u);
        dst[0] = make_float4(v[0],  v[1],  v[2],  v[3]);
        dst[1] = make_float4(v[4],  v[5],  v[6],  v[7]);
        dst[2] = make_float4(v[8],  v[9],  v[10], v[11]);
        dst[3] = make_float4(v[12], v[13], v[14], v[15]);
    }
}

// ---------------- attn[bh][l][d] = P_h[2048,2048] @ V_h[2048,64] ----------------
__global__ void __launch_bounds__(256) av_kernel()
{
    __shared__ float Ps[16][128];
    __shared__ float Vs[16][64];
    const int tid = threadIdx.x;
    const int tx = tid & 15, ty = tid >> 4;
    const int bh = blockIdx.z;
    const int mBase = blockIdx.y * 128;
    const float* P = g_scores + (size_t)bh * SS_;
    const float* V = g_qkv + (size_t)(64 + bh) * HEADSZ_;

    float acc[8][4] = {};

    for (int k0 = 0; k0 < 2048; k0 += 16) {
#pragma unroll
        for (int i = 0; i < 2; i++) {
            int f4 = tid + i * 256;
            int ar = f4 >> 2, ac = (f4 & 3) * 4;
            float4 vp = *(const float4*)(P + (size_t)(mBase + ar) * 2048 + k0 + ac);
            Ps[ac + 0][ar] = vp.x; Ps[ac + 1][ar] = vp.y;
            Ps[ac + 2][ar] = vp.z; Ps[ac + 3][ar] = vp.w;
        }
        {
            int vr = tid >> 4, vc = (tid & 15) * 4;
            *(float4*)&Vs[vr][vc] = *(const float4*)(V + (size_t)(k0 + vr) * 64 + vc);
        }
        __syncthreads();
#pragma unroll
        for (int kk = 0; kk < 16; kk++) {
            float a[8], b[4];
            *(float4*)&a[0] = *(float4*)&Ps[kk][ty * 8];
            *(float4*)&a[4] = *(float4*)&Ps[kk][ty * 8 + 4];
            *(float4*)&b[0] = *(float4*)&Vs[kk][tx * 4];
#pragma unroll
            for (int i = 0; i < 8; i++)
#pragma unroll
                for (int j = 0; j < 4; j++)
                    acc[i][j] += a[i] * b[j];
        }
        __syncthreads();
    }

    float* C = g_attn + (size_t)bh * HEADSZ_;
#pragma unroll
    for (int i = 0; i < 8; i++) {
        int row = mBase + ty * 8 + i;
        float4 v;
        v.x = acc[i][0]; v.y = acc[i][1]; v.z = acc[i][2]; v.w = acc[i][3];
        *(float4*)(C + (size_t)row * 64 + tx * 4) = v;
    }
}

// ---------------- head layout [bh][s][d] -> interleaved [m][d*16+h] ----------------
__global__ void __launch_bounds__(256) trans_attn_kernel()
{
    __shared__ float buf[8][1024];
    const int w = threadIdx.x >> 5, lane = threadIdx.x & 31;
    const int r = blockIdx.x * 8 + w;     // 0..4095 = b*2048+s
    const int b = r >> 11, s = r & 2047;

    const float* srcBase = g_attn + (size_t)b * 16u * HEADSZ_ + (size_t)s * 64;
#pragma unroll
    for (int h = 0; h < 16; h++) {
        const float* src = srcBase + (size_t)h * HEADSZ_;
#pragma unroll
        for (int half = 0; half < 2; half++) {
            int d = half * 32 + lane;
            buf[w][swz(d * 16 + h)] = src[d];
        }
    }
    __syncwarp();
    float* dst = g_attnT + (size_t)r * 1024;
#pragma unroll
    for (int i = 0; i < 8; i++) {
        int n0 = i * 128 + lane * 4;
        float4 v;
        v.x = buf[w][swz(n0 + 0)];
        v.y = buf[w][swz(n0 + 1)];
        v.z = buf[w][swz(n0 + 2)];
        v.w = buf[w][swz(n0 + 3)];
        *(float4*)(dst + n0) = v;
    }
}

// ---------------- launch ----------------
extern "C" void kernel_launch(void* const* d_in, const int* in_sizes, int n_in,
                              void* d_out, int out_size)
{
    const float* q  = (const float*)d_in[0];
    const float* k  = (const float*)d_in[1];
    const float* v  = (const float*)d_in[2];
    const float* Wq = (const float*)d_in[3];
    const float* bq = (const float*)d_in[4];
    const float* Wk = (const float*)d_in[5];
    const float* bk = (const float*)d_in[6];
    const float* Wv = (const float*)d_in[7];
    const float* bv = (const float*)d_in[8];
    const float* Wo = (const float*)d_in[9];
    const float* bo = (const float*)d_in[10];

    float* out = (float*)d_out;
    float* probs = (out_size >= 138412032) ? out + 4194304 : nullptr;

    dim3 gemmGrid(8, 32, 1);
    // Q/K/V projections -> g_lin3
    gemm_nk1024<<<gemmGrid, 256>>>(q, Wq, bq, nullptr, -1, 0);
    gemm_nk1024<<<gemmGrid, 256>>>(k, Wk, bk, nullptr, -1, 1);
    gemm_nk1024<<<gemmGrid, 256>>>(v, Wv, bv, nullptr, -1, 2);

    // interleave -> per-head contiguous
    trans_qkv_kernel<<<1536, 256>>>();

    // scores = QK^T / 8   (per b,h)
    qk_kernel<<<dim3(16, 16, 32), 256>>>();

    // softmax over head axis; writes probs output + normalized scores
    softmax_kernel<<<32768, 256>>>(probs);

    // attn = P @ V  (per b,h)
    av_kernel<<<dim3(1, 16, 32), 256>>>();

    // head layout -> interleaved for output projection
    trans_attn_kernel<<<512, 256>>>();

    // out = attnT @ Wo + bo
    gemm_nk1024<<<gemmGrid, 256>>>(nullptr, Wo, bo, out, 0, -1);
}

// round 4
// speedup vs baseline: 1.3509x; 1.3509x over previous
#include <cuda_runtime.h>
#include <mma.h>
using namespace nvcuda;

// Problem constants
#define B_   2
#define S_   2048
#define D_   1024
#define NH_  16
#define HD_  64
#define M_   4096           // B*S
#define SS_  4194304        // S*S
#define HEADSZ_ (2048*64)   // S*HD = 131072

// ---------------- scratch (__device__ globals; allocation-free) ----------------
__device__ float g_lin3[3u * 4096u * 1024u];     // 48 MB: q/k/v linear outputs [p][m][n]
__device__ float g_qkv[3u * 32u * 2048u * 64u];  // 48 MB: head layout [p*32+bh][s][d]
__device__ float g_scores[134217728u];           // 537 MB: [bh][l][n] scores -> probs
__device__ float g_attn[32u * 2048u * 64u];      // 16 MB: [bh][s][d]
__device__ float g_attnT[4096u * 1024u];         // 16 MB: interleaved [m][d*16+h]

__device__ __forceinline__ int swz(int n) { return n ^ ((n >> 5) & 31); }

// ============ tf32 GEMM: C[4096,1024] = A[4096,1024] @ W[1024,1024] + bias ============
// 128x128 CTA tile, 8 warps (2x4), warp tile 64x32, wmma m16n16k8 tf32.
__global__ void __launch_bounds__(256) gemm_wmma(const float* __restrict__ A,
                                                 const float* __restrict__ W,
                                                 const float* __restrict__ bias,
                                                 float* __restrict__ C,
                                                 int asel, int csel)
{
    if (asel >= 0) A = g_attnT;
    if (csel >= 0) C = g_lin3 + (size_t)csel * 4194304u;

    __shared__ float As[128][36];       // [m][k] chunk, k=32
    __shared__ float Bs[32][132];       // [k][n]
    __shared__ float stage[8][16][20];  // per-warp epilogue staging

    const int tid = threadIdx.x;
    const int warpId = tid >> 5, lane = tid & 31;
    const int wr = warpId >> 2, wc = warpId & 3;   // 2 x 4 warp grid
    const int mBase = blockIdx.y * 128, nBase = blockIdx.x * 128;

    wmma::fragment<wmma::accumulator, 16, 16, 8, float> acc[4][2];
#pragma unroll
    for (int i = 0; i < 4; i++)
#pragma unroll
        for (int j = 0; j < 2; j++) wmma::fill_fragment(acc[i][j], 0.0f);

    for (int k0 = 0; k0 < 1024; k0 += 32) {
#pragma unroll
        for (int p = 0; p < 4; p++) {
            int r = p * 32 + (tid >> 3);
            int c = (tid & 7) * 4;
            *(float4*)&As[r][c] = *(const float4*)(A + (size_t)(mBase + r) * 1024 + k0 + c);
        }
#pragma unroll
        for (int p = 0; p < 4; p++) {
            int r = p * 8 + (tid >> 5);
            int c = (tid & 31) * 4;
            *(float4*)&Bs[r][c] = *(const float4*)(W + (size_t)(k0 + r) * 1024 + nBase + c);
        }
        __syncthreads();

#pragma unroll
        for (int ks = 0; ks < 4; ks++) {
            wmma::fragment<wmma::matrix_a, 16, 16, 8, wmma::precision::tf32, wmma::row_major> af[4];
            wmma::fragment<wmma::matrix_b, 16, 16, 8, wmma::precision::tf32, wmma::row_major> bf[2];
#pragma unroll
            for (int i = 0; i < 4; i++) {
                wmma::load_matrix_sync(af[i], &As[wr * 64 + i * 16][ks * 8], 36);
#pragma unroll
                for (int t = 0; t < af[i].num_elements; t++) af[i].x[t] = wmma::__float_to_tf32(af[i].x[t]);
            }
#pragma unroll
            for (int j = 0; j < 2; j++) {
                wmma::load_matrix_sync(bf[j], &Bs[ks * 8][wc * 32 + j * 16], 132);
#pragma unroll
                for (int t = 0; t < bf[j].num_elements; t++) bf[j].x[t] = wmma::__float_to_tf32(bf[j].x[t]);
            }
#pragma unroll
            for (int i = 0; i < 4; i++)
#pragma unroll
                for (int j = 0; j < 2; j++)
                    wmma::mma_sync(acc[i][j], af[i], bf[j], acc[i][j]);
        }
        __syncthreads();
    }

    // Epilogue with bias add via per-warp staging
#pragma unroll
    for (int i = 0; i < 4; i++) {
#pragma unroll
        for (int j = 0; j < 2; j++) {
            wmma::store_matrix_sync(&stage[warpId][0][0], acc[i][j], 20, wmma::mem_row_major);
            __syncwarp();
            int r = lane >> 1, c0 = (lane & 1) * 8;
            int row = mBase + wr * 64 + i * 16 + r;
            int col = nBase + wc * 32 + j * 16 + c0;
            const float* sp = &stage[warpId][r][c0];
            float4 v0, v1;
            v0.x = sp[0] + bias[col + 0]; v0.y = sp[1] + bias[col + 1];
            v0.z = sp[2] + bias[col + 2]; v0.w = sp[3] + bias[col + 3];
            v1.x = sp[4] + bias[col + 4]; v1.y = sp[5] + bias[col + 5];
            v1.z = sp[6] + bias[col + 6]; v1.w = sp[7] + bias[col + 7];
            *(float4*)(C + (size_t)row * 1024 + col) = v0;
            *(float4*)(C + (size_t)row * 1024 + col + 4) = v1;
            __syncwarp();
        }
    }
}

// ---------------- interleaved [m][d*16+h] -> head layout [p*32+bh][s][d] ----------------
__global__ void __launch_bounds__(256) trans_qkv_kernel()
{
    __shared__ float buf[8][1024];
    const int w = threadIdx.x >> 5, lane = threadIdx.x & 31;
    const int r = blockIdx.x * 8 + w;
    const int p = r >> 12;
    const int bs = r & 4095;
    const int b = bs >> 11, s = bs & 2047;

    const float* src = g_lin3 + (size_t)r * 1024;
#pragma unroll
    for (int i = 0; i < 8; i++) {
        int n0 = i * 128 + lane * 4;
        float4 v = *(const float4*)(src + n0);
        buf[w][swz(n0 + 0)] = v.x;
        buf[w][swz(n0 + 1)] = v.y;
        buf[w][swz(n0 + 2)] = v.z;
        buf[w][swz(n0 + 3)] = v.w;
    }
    __syncwarp();
    float* dstBase = g_qkv + ((size_t)p * 32 + (size_t)b * 16) * HEADSZ_ + (size_t)s * 64;
#pragma unroll
    for (int h = 0; h < 16; h++) {
        float* dst = dstBase + (size_t)h * HEADSZ_;
#pragma unroll
        for (int half = 0; half < 2; half++) {
            int d = half * 32 + lane;
            dst[d] = buf[w][swz(d * 16 + h)];
        }
    }
}

// ============ tf32 QK: scores[bh][l][n] = (Q_h @ K_h^T) / 8 ============
// 128x128 tile, 8 warps (2x4), warp tile 64x32, K=64 in two 32-chunks.
__global__ void __launch_bounds__(256) qk_wmma()
{
    __shared__ float Qs[128][36];
    __shared__ float Ks[128][36];   // row-major [n][d]; read as col_major B
    const int tid = threadIdx.x;
    const int warpId = tid >> 5;
    const int wr = warpId >> 2, wc = warpId & 3;
    const int bh = blockIdx.z;
    const int mBase = blockIdx.y * 128, nBase = blockIdx.x * 128;
    const float* Q = g_qkv + (size_t)bh * HEADSZ_;
    const float* K = g_qkv + (size_t)(32 + bh) * HEADSZ_;

    wmma::fragment<wmma::accumulator, 16, 16, 8, float> acc[4][2];
#pragma unroll
    for (int i = 0; i < 4; i++)
#pragma unroll
        for (int j = 0; j < 2; j++) wmma::fill_fragment(acc[i][j], 0.0f);

    for (int k0 = 0; k0 < 64; k0 += 32) {
#pragma unroll
        for (int p = 0; p < 4; p++) {
            int r = p * 32 + (tid >> 3);
            int c = (tid & 7) * 4;
            *(float4*)&Qs[r][c] = *(const float4*)(Q + (size_t)(mBase + r) * 64 + k0 + c);
            *(float4*)&Ks[r][c] = *(const float4*)(K + (size_t)(nBase + r) * 64 + k0 + c);
        }
        __syncthreads();

#pragma unroll
        for (int ks = 0; ks < 4; ks++) {
            wmma::fragment<wmma::matrix_a, 16, 16, 8, wmma::precision::tf32, wmma::row_major> af[4];
            wmma::fragment<wmma::matrix_b, 16, 16, 8, wmma::precision::tf32, wmma::col_major> bf[2];
#pragma unroll
            for (int i = 0; i < 4; i++) {
                wmma::load_matrix_sync(af[i], &Qs[wr * 64 + i * 16][ks * 8], 36);
#pragma unroll
                for (int t = 0; t < af[i].num_elements; t++) af[i].x[t] = wmma::__float_to_tf32(af[i].x[t]);
            }
#pragma unroll
            for (int j = 0; j < 2; j++) {
                // col_major B: element (k, n') at Ks[n0 + n'][ks*8 + k]
                wmma::load_matrix_sync(bf[j], &Ks[wc * 32 + j * 16][ks * 8], 36);
#pragma unroll
                for (int t = 0; t < bf[j].num_elements; t++) bf[j].x[t] = wmma::__float_to_tf32(bf[j].x[t]);
            }
#pragma unroll
            for (int i = 0; i < 4; i++)
#pragma unroll
                for (int j = 0; j < 2; j++)
                    wmma::mma_sync(acc[i][j], af[i], bf[j], acc[i][j]);
        }
        __syncthreads();
    }

    float* Cp = g_scores + (size_t)bh * SS_;
#pragma unroll
    for (int i = 0; i < 4; i++)
#pragma unroll
        for (int j = 0; j < 2; j++) {
#pragma unroll
            for (int t = 0; t < acc[i][j].num_elements; t++) acc[i][j].x[t] *= 0.125f;
            wmma::store_matrix_sync(Cp + (size_t)(mBase + wr * 64 + i * 16) * 2048 +
                                    (nBase + wc * 32 + j * 16),
                                    acc[i][j], 2048, wmma::mem_row_major);
        }
}

// ---------------- softmax over the 16-head axis ----------------
__global__ void __launch_bounds__(256) softmax_kernel(float* __restrict__ probs_out)
{
    const size_t idx = (size_t)blockIdx.x * 256 + threadIdx.x;
    const int b = (int)(idx >> 22);
    const size_t ln = idx & 4194303u;
    const size_t base = (size_t)b * 16u * SS_ + ln;

    float v[16];
    float mx = -1e30f;
#pragma unroll
    for (int h = 0; h < 16; h++) {
        v[h] = g_scores[base + (size_t)h * SS_];
        mx = fmaxf(mx, v[h]);
    }
    float sum = 0.f;
#pragma unroll
    for (int h = 0; h < 16; h++) {
        v[h] = __expf(v[h] - mx);
        sum += v[h];
    }
    const float inv = 1.0f / sum;
#pragma unroll
    for (int h = 0; h < 16; h++) v[h] *= inv;

#pragma unroll
    for (int h = 0; h < 16; h++) g_scores[base + (size_t)h * SS_] = v[h];

    if (probs_out) {
        float4* dst = (float4*)(probs_out + idx * 16u);
        dst[0] = make_float4(v[0],  v[1],  v[2],  v[3]);
        dst[1] = make_float4(v[4],  v[5],  v[6],  v[7]);
        dst[2] = make_float4(v[8],  v[9],  v[10], v[11]);
        dst[3] = make_float4(v[12], v[13], v[14], v[15]);
    }
}

// ============ tf32 AV: attn[bh][l][d] = P_h[2048,2048] @ V_h[2048,64] ============
// 128x64 tile, 8 warps (4x2), warp tile 32x32.
__global__ void __launch_bounds__(256) av_wmma()
{
    __shared__ float Ps[128][36];
    __shared__ float Vs[32][68];
    const int tid = threadIdx.x;
    const int warpId = tid >> 5;
    const int wr = warpId >> 1, wc = warpId & 1;   // 4 x 2 warp grid
    const int bh = blockIdx.y;
    const int mBase = blockIdx.x * 128;
    const float* P = g_scores + (size_t)bh * SS_;
    const float* V = g_qkv + (size_t)(64 + bh) * HEADSZ_;

    wmma::fragment<wmma::accumulator, 16, 16, 8, float> acc[2][2];
#pragma unroll
    for (int i = 0; i < 2; i++)
#pragma unroll
        for (int j = 0; j < 2; j++) wmma::fill_fragment(acc[i][j], 0.0f);

    for (int k0 = 0; k0 < 2048; k0 += 32) {
#pragma unroll
        for (int p = 0; p < 4; p++) {
            int r = p * 32 + (tid >> 3);
            int c = (tid & 7) * 4;
            *(float4*)&Ps[r][c] = *(const float4*)(P + (size_t)(mBase + r) * 2048 + k0 + c);
        }
#pragma unroll
        for (int p = 0; p < 2; p++) {
            int r = p * 16 + (tid >> 4);
            int c = (tid & 15) * 4;
            *(float4*)&Vs[r][c] = *(const float4*)(V + (size_t)(k0 + r) * 64 + c);
        }
        __syncthreads();

#pragma unroll
        for (int ks = 0; ks < 4; ks++) {
            wmma::fragment<wmma::matrix_a, 16, 16, 8, wmma::precision::tf32, wmma::row_major> af[2];
            wmma::fragment<wmma::matrix_b, 16, 16, 8, wmma::precision::tf32, wmma::row_major> bf[2];
#pragma unroll
            for (int i = 0; i < 2; i++) {
                wmma::load_matrix_sync(af[i], &Ps[wr * 32 + i * 16][ks * 8], 36);
#pragma unroll
                for (int t = 0; t < af[i].num_elements; t++) af[i].x[t] = wmma::__float_to_tf32(af[i].x[t]);
            }
#pragma unroll
            for (int j = 0; j < 2; j++) {
                wmma::load_matrix_sync(bf[j], &Vs[ks * 8][wc * 32 + j * 16], 68);
#pragma unroll
                for (int t = 0; t < bf[j].num_elements; t++) bf[j].x[t] = wmma::__float_to_tf32(bf[j].x[t]);
            }
#pragma unroll
            for (int i = 0; i < 2; i++)
#pragma unroll
                for (int j = 0; j < 2; j++)
                    wmma::mma_sync(acc[i][j], af[i], bf[j], acc[i][j]);
        }
        __syncthreads();
    }

    float* C = g_attn + (size_t)bh * HEADSZ_;
#pragma unroll
    for (int i = 0; i < 2; i++)
#pragma unroll
        for (int j = 0; j < 2; j++)
            wmma::store_matrix_sync(C + (size_t)(mBase + wr * 32 + i * 16) * 64 +
                                    (wc * 32 + j * 16),
                                    acc[i][j], 64, wmma::mem_row_major);
}

// ---------------- head layout [bh][s][d] -> interleaved [m][d*16+h] ----------------
__global__ void __launch_bounds__(256) trans_attn_kernel()
{
    __shared__ float buf[8][1024];
    const int w = threadIdx.x >> 5, lane = threadIdx.x & 31;
    const int r = blockIdx.x * 8 + w;
    const int b = r >> 11, s = r & 2047;

    const float* srcBase = g_attn + (size_t)b * 16u * HEADSZ_ + (size_t)s * 64;
#pragma unroll
    for (int h = 0; h < 16; h++) {
        const float* src = srcBase + (size_t)h * HEADSZ_;
#pragma unroll
        for (int half = 0; half < 2; half++) {
            int d = half * 32 + lane;
            buf[w][swz(d * 16 + h)] = src[d];
        }
    }
    __syncwarp();
    float* dst = g_attnT + (size_t)r * 1024;
#pragma unroll
    for (int i = 0; i < 8; i++) {
        int n0 = i * 128 + lane * 4;
        float4 v;
        v.x = buf[w][swz(n0 + 0)];
        v.y = buf[w][swz(n0 + 1)];
        v.z = buf[w][swz(n0 + 2)];
        v.w = buf[w][swz(n0 + 3)];
        *(float4*)(dst + n0) = v;
    }
}

// ---------------- launch ----------------
extern "C" void kernel_launch(void* const* d_in, const int* in_sizes, int n_in,
                              void* d_out, int out_size)
{
    const float* q  = (const float*)d_in[0];
    const float* k  = (const float*)d_in[1];
    const float* v  = (const float*)d_in[2];
    const float* Wq = (const float*)d_in[3];
    const float* bq = (const float*)d_in[4];
    const float* Wk = (const float*)d_in[5];
    const float* bk = (const float*)d_in[6];
    const float* Wv = (const float*)d_in[7];
    const float* bv = (const float*)d_in[8];
    const float* Wo = (const float*)d_in[9];
    const float* bo = (const float*)d_in[10];

    float* out = (float*)d_out;
    float* probs = (out_size >= 138412032) ? out + 4194304 : nullptr;

    dim3 gemmGrid(8, 32, 1);
    gemm_wmma<<<gemmGrid, 256>>>(q, Wq, bq, nullptr, -1, 0);
    gemm_wmma<<<gemmGrid, 256>>>(k, Wk, bk, nullptr, -1, 1);
    gemm_wmma<<<gemmGrid, 256>>>(v, Wv, bv, nullptr, -1, 2);

    trans_qkv_kernel<<<1536, 256>>>();

    qk_wmma<<<dim3(16, 16, 32), 256>>>();

    softmax_kernel<<<32768, 256>>>(probs);

    av_wmma<<<dim3(16, 32), 256>>>();

    trans_attn_kernel<<<512, 256>>>();

    gemm_wmma<<<gemmGrid, 256>>>(nullptr, Wo, bo, out, 0, -1);
}